// round 3
// baseline (speedup 1.0000x reference)
#include <cuda_runtime.h>

#define Bb 256
#define Tt 256
#define Cc 384
#define Hh 64
#define BT (Bb*Tt)
#define K2 (Cc/2)          // 192 packed-k steps

typedef unsigned long long u64;

// Scratch for projected q, k, v: [B*T, H] each.
__device__ float g_q[BT*Hh];
__device__ float g_k[BT*Hh];
__device__ float g_v[BT*Hh];
// Pre-packed weights: [3][K2][Hh] u64, lo=W[2k][h], hi=W[2k+1][h].
__device__ u64 g_Wp[3 * K2 * Hh];

// ---- packed f32x2 helpers (FFMA2: one fma-pipe slot, two fp32 FMAs) ----
#define FMA2(d, a, b, c) \
    asm("fma.rn.f32x2 %0, %1, %2, %3;" : "=l"(d) : "l"(a), "l"(b), "l"(c))
#define MUL2(d, a, b) \
    asm("mul.rn.f32x2 %0, %1, %2;" : "=l"(d) : "l"(a), "l"(b))
#define PACK2(d, lo, hi) \
    asm("mov.b64 %0, {%1, %2};" : "=l"(d) : "r"(__float_as_uint(lo)), "r"(__float_as_uint(hi)))
#define UNPACK2(lo, hi, s) \
    { unsigned _a, _b; asm("mov.b64 {%0, %1}, %2;" : "=r"(_a), "=r"(_b) : "l"(s)); \
      lo = __uint_as_float(_a); hi = __uint_as_float(_b); }

// ---------------------------------------------------------------------------
// Kernel 0: pack W[q|k|v] into even/odd-k u64 pairs.
// ---------------------------------------------------------------------------
__global__ void wpack_kernel(const float* __restrict__ Wq,
                             const float* __restrict__ Wk,
                             const float* __restrict__ Wv)
{
    int idx = blockIdx.x * blockDim.x + threadIdx.x;   // 3*192*64 = 36864
    if (idx >= 3 * K2 * Hh) return;
    int m  = idx / (K2 * Hh);
    int k2 = (idx / Hh) % K2;
    int h  = idx % Hh;
    const float* W = (m == 0) ? Wq : (m == 1) ? Wk : Wv;
    u64 p;
    PACK2(p, W[(2 * k2) * Hh + h], W[(2 * k2 + 1) * Hh + h]);
    g_Wp[idx] = p;
}

// ---------------------------------------------------------------------------
// Kernel 1: fused q/k/v projection, FFMA2 over paired k.
// 32 rows/block (8 per thread), 256 threads, 2048 blocks.
// Accumulator pairs hold (even-k partial, odd-k partial); hadd at the end.
// ---------------------------------------------------------------------------
__global__ __launch_bounds__(256) void proj_kernel(
    const float* __restrict__ x)
{
    __shared__ float sx[32 * Cc];                      // 48 KB
    const int tid = threadIdx.x;
    const long rowbase = (long)blockIdx.x * 32;

    // Stage 32 rows of x: 32*384 = 12288 floats = 3072 float4, 12/thread.
    {
        const float4* x4 = (const float4*)(x + rowbase * Cc);
        float4* sx4 = (float4*)sx;
        #pragma unroll
        for (int i = 0; i < 12; i++)
            sx4[tid + i * 256] = x4[tid + i * 256];
    }
    __syncthreads();

    const int h  = tid & 63;
    const int r0 = (tid >> 6) * 8;                     // warp-uniform

    u64 aq[8], ak[8], av[8];
    #pragma unroll
    for (int i = 0; i < 8; i++) { aq[i] = 0ull; ak[i] = 0ull; av[i] = 0ull; }

    const u64* wq2 = g_Wp + 0 * K2 * Hh + h;
    const u64* wk2 = g_Wp + 1 * K2 * Hh + h;
    const u64* wv2 = g_Wp + 2 * K2 * Hh + h;
    // x pairs: &sx[row*Cc + 2*k2] as u64 -> index row*(Cc/2) + k2.
    const u64* sx2 = (const u64*)sx;

    #pragma unroll 2
    for (int k2 = 0; k2 < K2; k2++) {
        const u64 wq = wq2[k2 * Hh];
        const u64 wk = wk2[k2 * Hh];
        const u64 wv = wv2[k2 * Hh];
        #pragma unroll
        for (int i = 0; i < 8; i++) {
            const u64 xv = sx2[(r0 + i) * K2 + k2];    // warp-broadcast LDS.64
            FMA2(aq[i], xv, wq, aq[i]);
            FMA2(ak[i], xv, wk, ak[i]);
            FMA2(av[i], xv, wv, av[i]);
        }
    }

    #pragma unroll
    for (int i = 0; i < 8; i++) {
        const long o = (rowbase + r0 + i) * Hh + h;
        float lo, hi;
        UNPACK2(lo, hi, aq[i]); g_q[o] = lo + hi;
        UNPACK2(lo, hi, ak[i]); g_k[o] = lo + hi;
        UNPACK2(lo, hi, av[i]); g_v[o] = lo + hi;
    }
}

// ---------------------------------------------------------------------------
// Kernel 2: causal attention with FFMA2 over paired head-dims.
// One block per batch; K,V (128 KB) in dynamic smem; one thread per query.
// q and o live as 32 u64 (d,d+1) pairs. Online softmax, rescale-on-new-max.
// ---------------------------------------------------------------------------
extern __shared__ float attn_smem[];

__global__ __launch_bounds__(256) void attn_kernel(float* __restrict__ out)
{
    float* sk = attn_smem;            // [T][H]
    float* sv = attn_smem + Tt * Hh;  // [T][H]

    const int b   = blockIdx.x;
    const int tid = threadIdx.x;

    {
        const float4* gk4 = (const float4*)(g_k + (long)b * Tt * Hh);
        const float4* gv4 = (const float4*)(g_v + (long)b * Tt * Hh);
        float4* sk4 = (float4*)sk;
        float4* sv4 = (float4*)sv;
        #pragma unroll
        for (int i = 0; i < 16; i++) {
            sk4[tid + i * 256] = gk4[tid + i * 256];
            sv4[tid + i * 256] = gv4[tid + i * 256];
        }
    }
    __syncthreads();

    const int r = tid;  // query row

    // q row as 32 packed pairs.
    u64 q2[32];
    {
        const u64* gq2 = (const u64*)(g_q + ((long)b * Tt + r) * Hh);
        #pragma unroll
        for (int i = 0; i < 32; i++) q2[i] = gq2[i];
    }

    u64 o2[32];
    #pragma unroll
    for (int i = 0; i < 32; i++) o2[i] = 0ull;

    float m = -1e30f;
    float l = 0.f;
    const float scale = rsqrtf((float)Cc);   // C^-0.5 (384), per reference

    for (int j = 0; j <= r; j++) {
        // s = q . k_j : 4 FFMA2 chains of depth 8 (LDS.128 via ulonglong2).
        const ulonglong2* kj = (const ulonglong2*)(sk + j * Hh);
        u64 c0 = 0ull, c1 = 0ull, c2 = 0ull, c3 = 0ull;
        #pragma unroll
        for (int i = 0; i < 8; i++) {
            const ulonglong2 ka = kj[2 * i + 0];
            const ulonglong2 kb = kj[2 * i + 1];
            FMA2(c0, q2[4 * i + 0], ka.x, c0);
            FMA2(c1, q2[4 * i + 1], ka.y, c1);
            FMA2(c2, q2[4 * i + 2], kb.x, c2);
            FMA2(c3, q2[4 * i + 3], kb.y, c3);
        }
        float s;
        {
            float a0, a1, b0, b1, d0, d1, e0, e1;
            UNPACK2(a0, a1, c0); UNPACK2(b0, b1, c1);
            UNPACK2(d0, d1, c2); UNPACK2(e0, e1, c3);
            s = (((a0 + a1) + (b0 + b1)) + ((d0 + d1) + (e0 + e1))) * scale;
        }

        float p;
        if (s > m) {
            const float corr = __expf(m - s);          // first iter: 0
            l *= corr;
            u64 corr2; PACK2(corr2, corr, corr);
            #pragma unroll
            for (int i = 0; i < 32; i++) MUL2(o2[i], o2[i], corr2);
            m = s;
            p = 1.0f;
        } else {
            p = __expf(s - m);
        }
        l += p;

        u64 p2; PACK2(p2, p, p);
        const ulonglong2* vj = (const ulonglong2*)(sv + j * Hh);
        #pragma unroll
        for (int i = 0; i < 16; i++) {
            const ulonglong2 vv = vj[i];
            FMA2(o2[2 * i + 0], p2, vv.x, o2[2 * i + 0]);
            FMA2(o2[2 * i + 1], p2, vv.y, o2[2 * i + 1]);
        }
    }

    const float inv = 1.0f / l;
    u64 inv2; PACK2(inv2, inv, inv);
    u64* out2 = (u64*)(out + ((long)b * Tt + r) * Hh);
    #pragma unroll
    for (int i = 0; i < 32; i++) {
        u64 res; MUL2(res, o2[i], inv2);
        out2[i] = res;
    }
}

// ---------------------------------------------------------------------------
// Launch
// ---------------------------------------------------------------------------
extern "C" void kernel_launch(void* const* d_in, const int* in_sizes, int n_in,
                              void* d_out, int out_size)
{
    const float* x  = (const float*)d_in[0];
    const float* Wq = (const float*)d_in[1];
    const float* Wk = (const float*)d_in[2];
    const float* Wv = (const float*)d_in[3];
    float* out = (float*)d_out;

    (void)in_sizes; (void)n_in; (void)out_size;

    const int attn_smem_bytes = 2 * Tt * Hh * (int)sizeof(float);  // 128 KB
    cudaFuncSetAttribute(attn_kernel,
                         cudaFuncAttributeMaxDynamicSharedMemorySize,
                         attn_smem_bytes);

    wpack_kernel<<<(3 * K2 * Hh + 255) / 256, 256>>>(Wq, Wk, Wv);
    proj_kernel<<<BT / 32, 256>>>(x);
    attn_kernel<<<Bb, 256, attn_smem_bytes>>>(out);
}

// round 6
// speedup vs baseline: 1.9731x; 1.9731x over previous
#include <cuda_runtime.h>
#include <cuda_bf16.h>
#include <cstdint>

#define Bb 256
#define Tt 256
#define Cc 384
#define Hh 64
#define BT (Bb*Tt)
#define Ncat 192
#define KCH 32
#define NCHUNK (Cc/KCH)        // 12
#define BCHUNK_U32 6144        // packed B frags per K-chunk (24 n8-tiles x 2 ksteps x 2 halves x 64)

// Scratch
__device__ float g_q[BT*Hh];
__device__ float g_k[BT*Hh];
__device__ float g_v[BT*Hh];
__device__ uint32_t g_Bp[NCHUNK * BCHUNK_U32];   // fragment-layout packed weights

// pack two floats as bf16x2: low half = a (smaller k), high half = b
__device__ __forceinline__ uint32_t pack_bf16(float a, float b) {
    uint32_t r;
    asm("cvt.rn.bf16x2.f32 %0, %1, %2;" : "=r"(r) : "f"(b), "f"(a));
    return r;
}

__device__ __forceinline__ void split_pair(float xx, float yy, uint32_t& hi, uint32_t& lo) {
    const float hx = __bfloat162float(__float2bfloat16(xx));
    const float hy = __bfloat162float(__float2bfloat16(yy));
    hi = pack_bf16(xx, yy);
    lo = pack_bf16(xx - hx, yy - hy);
}

__device__ __forceinline__ void mma_bf16(float* c, const uint32_t* a, uint2 b) {
    asm volatile("mma.sync.aligned.m16n8k16.row.col.f32.bf16.bf16.f32 "
        "{%0,%1,%2,%3}, {%4,%5,%6,%7}, {%8,%9}, {%0,%1,%2,%3};"
        : "+f"(c[0]), "+f"(c[1]), "+f"(c[2]), "+f"(c[3])
        : "r"(a[0]), "r"(a[1]), "r"(a[2]), "r"(a[3]), "r"(b.x), "r"(b.y));
}

// ---------------------------------------------------------------------------
// Kernel 0: pack W into per-chunk fragment layout, bf16 hi/lo.
// Layout: [chunk][j(24)][s(2)][h(2)][lane(32)*2 + rr]
//   b0 (rr=0) = {W[k][n], W[k+1][n]}, k = chunk*32 + s*16 + 2*ct
//   b1 (rr=1) = same with k += 8;  n = j*8 + (lane>>2), ct = lane&3
// ---------------------------------------------------------------------------
__global__ void wprep_kernel(const float* __restrict__ Wq,
                             const float* __restrict__ Wk,
                             const float* __restrict__ Wv)
{
    const int gid = blockIdx.x * blockDim.x + threadIdx.x;
    if (gid >= NCHUNK * BCHUNK_U32) return;
    const int chunk = gid / BCHUNK_U32;
    const int t  = gid % BCHUNK_U32;
    const int j  = t >> 8;
    const int s  = (t >> 7) & 1;
    const int h  = (t >> 6) & 1;
    const int l  = (t >> 1) & 31;
    const int rr = t & 1;
    const int gr = l >> 2, ct = l & 3;
    const int n  = j * 8 + gr;
    const int k  = chunk * 32 + s * 16 + 2 * ct + rr * 8;
    const float* W = (n < 64) ? Wq : (n < 128) ? Wk : Wv;
    const int hc = n & 63;
    const float w0 = W[k * Hh + hc];
    const float w1 = W[(k + 1) * Hh + hc];
    uint32_t outv;
    if (h == 0) {
        outv = pack_bf16(w0, w1);
    } else {
        const float h0 = __bfloat162float(__float2bfloat16(w0));
        const float h1 = __bfloat162float(__float2bfloat16(w1));
        outv = pack_bf16(w0 - h0, w1 - h1);
    }
    g_Bp[gid] = outv;
}

// ---------------------------------------------------------------------------
// Kernel 1: projection via mma.sync bf16 3-pass (hh + hl + lh).
// CTA: 128 rows x 192 cols, 8 warps as 4(M) x 2(N) -> warp tile 32x96.
// K in 12 chunks of 32, double-buffered smem.
// smem (u32): A buf b at b*4096 (hi +0, lo +2048); B buf b at 8192 + b*6144.
// ---------------------------------------------------------------------------
#define PSM_U32 (2*4096 + 2*BCHUNK_U32)   // 20480 u32 = 80 KB

extern __shared__ char dynsm[];

__device__ __forceinline__ void ldgA(const float* __restrict__ x, long rowbase,
                                     int c, int tid, float4 av[4]) {
    #pragma unroll
    for (int i = 0; i < 4; i++) {
        const int idx = tid + i * 256;
        const int row = idx >> 3, c4 = idx & 7;
        av[i] = *(const float4*)(x + (rowbase + row) * Cc + c * KCH + c4 * 4);
    }
}

__device__ __forceinline__ void stsA(uint32_t* abuf, int tid, const float4 av[4]) {
    #pragma unroll
    for (int i = 0; i < 4; i++) {
        const int idx = tid + i * 256;
        const int row = idx >> 3, c4 = idx & 7;
        const int k2 = c4 * 2;                 // first of two k2 pairs
        const int base_i = ((row >> 4) * 2 + (k2 >> 3)) * 128;
        const int r = ((row >> 3) & 1) + (((k2 >> 2) & 1) << 1);
        const int lane4 = ((row & 7) << 2) | (k2 & 3);
        const int off = base_i + lane4 * 4 + r;
        uint32_t hi0, lo0, hi1, lo1;
        split_pair(av[i].x, av[i].y, hi0, lo0);
        split_pair(av[i].z, av[i].w, hi1, lo1);
        abuf[off]            = hi0;
        abuf[2048 + off]     = lo0;
        abuf[off + 4]        = hi1;
        abuf[2048 + off + 4] = lo1;
    }
}

__device__ __forceinline__ void ldgB(int c, int tid, float4 bv[6]) {
    const float4* src = (const float4*)(g_Bp + c * BCHUNK_U32);
    #pragma unroll
    for (int i = 0; i < 6; i++) bv[i] = src[tid + i * 256];
}

__device__ __forceinline__ void stsB(uint32_t* bbuf, int tid, const float4 bv[6]) {
    float4* dst = (float4*)bbuf;
    #pragma unroll
    for (int i = 0; i < 6; i++) dst[tid + i * 256] = bv[i];
}

__global__ __launch_bounds__(256) void proj_kernel(const float* __restrict__ x)
{
    uint32_t* psm = (uint32_t*)dynsm;
    const int tid  = threadIdx.x;
    const long rowbase = (long)blockIdx.x * 128;
    const int warp = tid >> 5, lane = tid & 31;
    const int mw = warp & 3, nw = warp >> 2;
    const int gr = lane >> 2, ct = lane & 3;

    float acc[2][12][4];
    #pragma unroll
    for (int im = 0; im < 2; im++)
        #pragma unroll
        for (int j = 0; j < 12; j++)
            #pragma unroll
            for (int r = 0; r < 4; r++) acc[im][j][r] = 0.f;

    // Prologue: stage chunk 0 into buffer 0.
    {
        float4 av[4], bv[6];
        ldgA(x, rowbase, 0, tid, av);
        ldgB(0, tid, bv);
        stsA(psm, tid, av);
        stsB(psm + 8192, tid, bv);
    }
    __syncthreads();

    for (int c = 0; c < NCHUNK; c++) {
        float4 av[4], bv[6];
        const bool more = (c + 1 < NCHUNK);
        if (more) {
            ldgA(x, rowbase, c + 1, tid, av);
            ldgB(c + 1, tid, bv);
        }

        const uint32_t* abuf = psm + (c & 1) * 4096;
        const uint32_t* bbuf = psm + 8192 + (c & 1) * BCHUNK_U32;

        #pragma unroll
        for (int s = 0; s < 2; s++) {
            uint32_t ah[2][4], al[2][4];
            #pragma unroll
            for (int im = 0; im < 2; im++) {
                const int base = ((mw * 2 + im) * 2 + s) * 128 + lane * 4;
                const uint4 vh = *(const uint4*)(abuf + base);
                const uint4 vl = *(const uint4*)(abuf + 2048 + base);
                ah[im][0] = vh.x; ah[im][1] = vh.y; ah[im][2] = vh.z; ah[im][3] = vh.w;
                al[im][0] = vl.x; al[im][1] = vl.y; al[im][2] = vl.z; al[im][3] = vl.w;
            }
            #pragma unroll
            for (int j = 0; j < 12; j++) {
                const int jj = nw * 12 + j;
                const uint32_t* bp = bbuf + ((jj * 2 + s) * 2) * 64 + lane * 2;
                const uint2 bh = *(const uint2*)(bp);
                const uint2 bl = *(const uint2*)(bp + 64);
                #pragma unroll
                for (int im = 0; im < 2; im++) {
                    mma_bf16(acc[im][j], ah[im], bh);   // hi*hi
                    mma_bf16(acc[im][j], ah[im], bl);   // hi*lo
                    mma_bf16(acc[im][j], al[im], bh);   // lo*hi
                }
            }
        }

        if (more) {
            uint32_t* abn = psm + ((c + 1) & 1) * 4096;
            uint32_t* bbn = psm + 8192 + ((c + 1) & 1) * BCHUNK_U32;
            stsA(abn, tid, av);
            stsB(bbn, tid, bv);
        }
        __syncthreads();
    }

    // Epilogue: scatter accumulators to g_q / g_k / g_v.
    #pragma unroll
    for (int im = 0; im < 2; im++) {
        #pragma unroll
        for (int j = 0; j < 12; j++) {
            const int jj = nw * 12 + j;
            const int n0 = jj * 8 + 2 * ct;
            float* dst = (n0 < 64) ? g_q : (n0 < 128) ? g_k : g_v;
            const int hc = n0 & 63;
            const long row0 = rowbase + mw * 32 + im * 16 + gr;
            *(float2*)(dst + row0 * Hh + hc)       = make_float2(acc[im][j][0], acc[im][j][1]);
            *(float2*)(dst + (row0 + 8) * Hh + hc) = make_float2(acc[im][j][2], acc[im][j][3]);
        }
    }
}

// ---------------------------------------------------------------------------
// Kernel 2: causal attention (R1 version, known good).
// ---------------------------------------------------------------------------
__global__ __launch_bounds__(256) void attn_kernel(float* __restrict__ out)
{
    float* sk = (float*)dynsm;
    float* sv = (float*)dynsm + Tt * Hh;

    const int b   = blockIdx.x;
    const int tid = threadIdx.x;

    {
        const float4* gk4 = (const float4*)(g_k + (long)b * Tt * Hh);
        const float4* gv4 = (const float4*)(g_v + (long)b * Tt * Hh);
        float4* sk4 = (float4*)sk;
        float4* sv4 = (float4*)sv;
        #pragma unroll
        for (int i = 0; i < 16; i++) {
            sk4[tid + i * 256] = gk4[tid + i * 256];
            sv4[tid + i * 256] = gv4[tid + i * 256];
        }
    }
    __syncthreads();

    const int r = tid;

    float4 q[16];
    {
        const float4* gq4 = (const float4*)(g_q + ((long)b * Tt + r) * Hh);
        #pragma unroll
        for (int i = 0; i < 16; i++) q[i] = gq4[i];
    }

    float o[Hh];
    #pragma unroll
    for (int i = 0; i < Hh; i++) o[i] = 0.f;

    float m = -1e30f;
    float l = 0.f;
    const float scale = rsqrtf((float)Cc);   // C^-0.5 (384), per reference

    for (int j = 0; j <= r; j++) {
        const float4* kj = (const float4*)(sk + j * Hh);
        float s0 = 0.f, s1 = 0.f, s2 = 0.f, s3 = 0.f;
        #pragma unroll
        for (int i = 0; i < 16; i++) {
            const float4 kv = kj[i];
            const float4 qi = q[i];
            s0 = fmaf(qi.x, kv.x, s0);
            s1 = fmaf(qi.y, kv.y, s1);
            s2 = fmaf(qi.z, kv.z, s2);
            s3 = fmaf(qi.w, kv.w, s3);
        }
        const float s = ((s0 + s1) + (s2 + s3)) * scale;

        float p;
        if (s > m) {
            const float corr = __expf(m - s);
            l *= corr;
            #pragma unroll
            for (int i = 0; i < Hh; i++) o[i] *= corr;
            m = s;
            p = 1.0f;
        } else {
            p = __expf(s - m);
        }
        l += p;

        const float4* vj = (const float4*)(sv + j * Hh);
        #pragma unroll
        for (int i = 0; i < 16; i++) {
            const float4 vv = vj[i];
            o[i * 4 + 0] = fmaf(p, vv.x, o[i * 4 + 0]);
            o[i * 4 + 1] = fmaf(p, vv.y, o[i * 4 + 1]);
            o[i * 4 + 2] = fmaf(p, vv.z, o[i * 4 + 2]);
            o[i * 4 + 3] = fmaf(p, vv.w, o[i * 4 + 3]);
        }
    }

    const float inv = 1.0f / l;
    float4* out4 = (float4*)(out + ((long)b * Tt + r) * Hh);
    #pragma unroll
    for (int i = 0; i < 16; i++) {
        out4[i] = make_float4(o[i * 4 + 0] * inv, o[i * 4 + 1] * inv,
                              o[i * 4 + 2] * inv, o[i * 4 + 3] * inv);
    }
}

// ---------------------------------------------------------------------------
// Launch
// ---------------------------------------------------------------------------
extern "C" void kernel_launch(void* const* d_in, const int* in_sizes, int n_in,
                              void* d_out, int out_size)
{
    const float* x  = (const float*)d_in[0];
    const float* Wq = (const float*)d_in[1];
    const float* Wk = (const float*)d_in[2];
    const float* Wv = (const float*)d_in[3];
    float* out = (float*)d_out;

    (void)in_sizes; (void)n_in; (void)out_size;

    const int proj_smem = PSM_U32 * 4;                       // 80 KB
    const int attn_smem = 2 * Tt * Hh * (int)sizeof(float);  // 128 KB
    cudaFuncSetAttribute(proj_kernel,
                         cudaFuncAttributeMaxDynamicSharedMemorySize, proj_smem);
    cudaFuncSetAttribute(attn_kernel,
                         cudaFuncAttributeMaxDynamicSharedMemorySize, attn_smem);

    wprep_kernel<<<(NCHUNK * BCHUNK_U32 + 255) / 256, 256>>>(Wq, Wk, Wv);
    proj_kernel<<<BT / 128, 256, proj_smem>>>(x);
    attn_kernel<<<Bb, 256, attn_smem>>>(out);
}

// round 7
// speedup vs baseline: 3.1930x; 1.6183x over previous
#include <cuda_runtime.h>
#include <cuda_bf16.h>
#include <cstdint>

#define Bb 256
#define Tt 256
#define Cc 384
#define Hh 64
#define BT (Bb*Tt)
#define Ncat 192
#define KCH 32
#define NCHUNK (Cc/KCH)        // 12
#define BCHUNK_U32 6144

// Scratch
__device__ float    g_v[BT*Hh];          // V fp32 [row][h]
__device__ uint32_t g_qph[BT*32];        // Q bf16 hi, pairs along h
__device__ uint32_t g_qpl[BT*32];        // Q bf16 lo
__device__ uint32_t g_kph[BT*32];        // K bf16 hi
__device__ uint32_t g_kpl[BT*32];        // K bf16 lo
__device__ uint32_t g_Bp[NCHUNK * BCHUNK_U32];

// pack two floats as bf16x2: low half = a, high half = b
__device__ __forceinline__ uint32_t pack_bf16(float a, float b) {
    uint32_t r;
    asm("cvt.rn.bf16x2.f32 %0, %1, %2;" : "=r"(r) : "f"(b), "f"(a));
    return r;
}

__device__ __forceinline__ void split_pair(float xx, float yy, uint32_t& hi, uint32_t& lo) {
    const float hx = __bfloat162float(__float2bfloat16(xx));
    const float hy = __bfloat162float(__float2bfloat16(yy));
    hi = pack_bf16(xx, yy);
    lo = pack_bf16(xx - hx, yy - hy);
}

__device__ __forceinline__ void mma_bf16(float* c, const uint32_t* a, uint2 b) {
    asm volatile("mma.sync.aligned.m16n8k16.row.col.f32.bf16.bf16.f32 "
        "{%0,%1,%2,%3}, {%4,%5,%6,%7}, {%8,%9}, {%0,%1,%2,%3};"
        : "+f"(c[0]), "+f"(c[1]), "+f"(c[2]), "+f"(c[3])
        : "r"(a[0]), "r"(a[1]), "r"(a[2]), "r"(a[3]), "r"(b.x), "r"(b.y));
}

// ---------------------------------------------------------------------------
// Kernel 0: pack W into per-chunk fragment layout, bf16 hi/lo. (unchanged)
// ---------------------------------------------------------------------------
__global__ void wprep_kernel(const float* __restrict__ Wq,
                             const float* __restrict__ Wk,
                             const float* __restrict__ Wv)
{
    const int gid = blockIdx.x * blockDim.x + threadIdx.x;
    if (gid >= NCHUNK * BCHUNK_U32) return;
    const int chunk = gid / BCHUNK_U32;
    const int t  = gid % BCHUNK_U32;
    const int j  = t >> 8;
    const int s  = (t >> 7) & 1;
    const int h  = (t >> 6) & 1;
    const int l  = (t >> 1) & 31;
    const int rr = t & 1;
    const int gr = l >> 2, ct = l & 3;
    const int n  = j * 8 + gr;
    const int k  = chunk * 32 + s * 16 + 2 * ct + rr * 8;
    const float* W = (n < 64) ? Wq : (n < 128) ? Wk : Wv;
    const int hc = n & 63;
    const float w0 = W[k * Hh + hc];
    const float w1 = W[(k + 1) * Hh + hc];
    uint32_t outv;
    if (h == 0) {
        outv = pack_bf16(w0, w1);
    } else {
        const float h0 = __bfloat162float(__float2bfloat16(w0));
        const float h1 = __bfloat162float(__float2bfloat16(w1));
        outv = pack_bf16(w0 - h0, w1 - h1);
    }
    g_Bp[gid] = outv;
}

// ---------------------------------------------------------------------------
// Kernel 1: projection via mma.sync bf16 3-pass. Epilogue writes Q,K as
// bf16 hi/lo packed pairs (mma-ready) and V as fp32.
// ---------------------------------------------------------------------------
#define PSM_U32 (2*4096 + 2*BCHUNK_U32)   // 80 KB

extern __shared__ char dynsm[];

__device__ __forceinline__ void ldgA(const float* __restrict__ x, long rowbase,
                                     int c, int tid, float4 av[4]) {
    #pragma unroll
    for (int i = 0; i < 4; i++) {
        const int idx = tid + i * 256;
        const int row = idx >> 3, c4 = idx & 7;
        av[i] = *(const float4*)(x + (rowbase + row) * Cc + c * KCH + c4 * 4);
    }
}

__device__ __forceinline__ void stsA(uint32_t* abuf, int tid, const float4 av[4]) {
    #pragma unroll
    for (int i = 0; i < 4; i++) {
        const int idx = tid + i * 256;
        const int row = idx >> 3, c4 = idx & 7;
        const int k2 = c4 * 2;
        const int base_i = ((row >> 4) * 2 + (k2 >> 3)) * 128;
        const int r = ((row >> 3) & 1) + (((k2 >> 2) & 1) << 1);
        const int lane4 = ((row & 7) << 2) | (k2 & 3);
        const int off = base_i + lane4 * 4 + r;
        uint32_t hi0, lo0, hi1, lo1;
        split_pair(av[i].x, av[i].y, hi0, lo0);
        split_pair(av[i].z, av[i].w, hi1, lo1);
        abuf[off]            = hi0;
        abuf[2048 + off]     = lo0;
        abuf[off + 4]        = hi1;
        abuf[2048 + off + 4] = lo1;
    }
}

__device__ __forceinline__ void ldgB(int c, int tid, float4 bv[6]) {
    const float4* src = (const float4*)(g_Bp + c * BCHUNK_U32);
    #pragma unroll
    for (int i = 0; i < 6; i++) bv[i] = src[tid + i * 256];
}

__device__ __forceinline__ void stsB(uint32_t* bbuf, int tid, const float4 bv[6]) {
    float4* dst = (float4*)bbuf;
    #pragma unroll
    for (int i = 0; i < 6; i++) dst[tid + i * 256] = bv[i];
}

__global__ __launch_bounds__(256) void proj_kernel(const float* __restrict__ x)
{
    uint32_t* psm = (uint32_t*)dynsm;
    const int tid  = threadIdx.x;
    const long rowbase = (long)blockIdx.x * 128;
    const int warp = tid >> 5, lane = tid & 31;
    const int mw = warp & 3, nw = warp >> 2;
    const int gr = lane >> 2, ct = lane & 3;

    float acc[2][12][4];
    #pragma unroll
    for (int im = 0; im < 2; im++)
        #pragma unroll
        for (int j = 0; j < 12; j++)
            #pragma unroll
            for (int r = 0; r < 4; r++) acc[im][j][r] = 0.f;

    {
        float4 av[4], bv[6];
        ldgA(x, rowbase, 0, tid, av);
        ldgB(0, tid, bv);
        stsA(psm, tid, av);
        stsB(psm + 8192, tid, bv);
    }
    __syncthreads();

    for (int c = 0; c < NCHUNK; c++) {
        float4 av[4], bv[6];
        const bool more = (c + 1 < NCHUNK);
        if (more) {
            ldgA(x, rowbase, c + 1, tid, av);
            ldgB(c + 1, tid, bv);
        }

        const uint32_t* abuf = psm + (c & 1) * 4096;
        const uint32_t* bbuf = psm + 8192 + (c & 1) * BCHUNK_U32;

        #pragma unroll
        for (int s = 0; s < 2; s++) {
            uint32_t ah[2][4], al[2][4];
            #pragma unroll
            for (int im = 0; im < 2; im++) {
                const int base = ((mw * 2 + im) * 2 + s) * 128 + lane * 4;
                const uint4 vh = *(const uint4*)(abuf + base);
                const uint4 vl = *(const uint4*)(abuf + 2048 + base);
                ah[im][0] = vh.x; ah[im][1] = vh.y; ah[im][2] = vh.z; ah[im][3] = vh.w;
                al[im][0] = vl.x; al[im][1] = vl.y; al[im][2] = vl.z; al[im][3] = vl.w;
            }
            #pragma unroll
            for (int j = 0; j < 12; j++) {
                const int jj = nw * 12 + j;
                const uint32_t* bp = bbuf + ((jj * 2 + s) * 2) * 64 + lane * 2;
                const uint2 bh = *(const uint2*)(bp);
                const uint2 bl = *(const uint2*)(bp + 64);
                #pragma unroll
                for (int im = 0; im < 2; im++) {
                    mma_bf16(acc[im][j], ah[im], bh);
                    mma_bf16(acc[im][j], ah[im], bl);
                    mma_bf16(acc[im][j], al[im], bh);
                }
            }
        }

        if (more) {
            uint32_t* abn = psm + ((c + 1) & 1) * 4096;
            uint32_t* bbn = psm + 8192 + ((c + 1) & 1) * BCHUNK_U32;
            stsA(abn, tid, av);
            stsB(bbn, tid, bv);
        }
        __syncthreads();
    }

    // Epilogue: q,k -> bf16 hi/lo packed pairs; v -> fp32.
    #pragma unroll
    for (int im = 0; im < 2; im++) {
        #pragma unroll
        for (int j = 0; j < 12; j++) {
            const int jj = nw * 12 + j;
            const int n0 = jj * 8 + 2 * ct;
            const long row0 = rowbase + mw * 32 + im * 16 + gr;
            if (n0 < 128) {
                uint32_t* dh = (n0 < 64) ? g_qph : g_kph;
                uint32_t* dl = (n0 < 64) ? g_qpl : g_kpl;
                const int hp = (jj & 7) * 4 + ct;
                uint32_t hi0, lo0, hi1, lo1;
                split_pair(acc[im][j][0], acc[im][j][1], hi0, lo0);
                split_pair(acc[im][j][2], acc[im][j][3], hi1, lo1);
                dh[row0 * 32 + hp]       = hi0;
                dl[row0 * 32 + hp]       = lo0;
                dh[(row0 + 8) * 32 + hp] = hi1;
                dl[(row0 + 8) * 32 + hp] = lo1;
            } else {
                const int hc = n0 & 63;
                *(float2*)(g_v + row0 * Hh + hc)       = make_float2(acc[im][j][0], acc[im][j][1]);
                *(float2*)(g_v + (row0 + 8) * Hh + hc) = make_float2(acc[im][j][2], acc[im][j][3]);
            }
        }
    }
}

// ---------------------------------------------------------------------------
// Kernel 2: flash attention via mma.sync bf16 3-pass.
// 1 CTA per batch, 8 warps. Warp w owns query rows w + 8i (balanced causal).
// smem: skh[256][36], skl[256][36], svh[64][132], svl[64][132] (u32, padded).
// ---------------------------------------------------------------------------
#define SKH 0
#define SKL 9216
#define SVH 18432
#define SVL (18432 + 8448)
#define ASM_U32 (18432 + 2*8448)   // 35328 u32 = 141312 B

__global__ __launch_bounds__(256) void attn_kernel(float* __restrict__ out)
{
    uint32_t* sm = (uint32_t*)dynsm;
    uint32_t* skh = sm + SKH;
    uint32_t* skl = sm + SKL;
    uint32_t* svh = sm + SVH;
    uint32_t* svl = sm + SVL;

    const int b   = blockIdx.x;
    const int tid = threadIdx.x;

    // Stage K hi/lo: [256][32] u32 -> [256][36] padded, via float4.
    {
        const uint4* gh = (const uint4*)(g_kph + (size_t)b * 8192);
        const uint4* gl = (const uint4*)(g_kpl + (size_t)b * 8192);
        #pragma unroll
        for (int i = 0; i < 8; i++) {
            const int idx = tid + i * 256;       // 0..2047
            const int row = idx >> 3, c4 = (idx & 7) * 4;
            *(uint4*)(skh + row * 36 + c4) = gh[idx];
            *(uint4*)(skl + row * 36 + c4) = gl[idx];
        }
    }
    // Stage V: transpose+split fp32 [key][h] -> bf16 pairs [h][keypair].
    {
        const float* gv = g_v + (size_t)b * Tt * Hh;
        const int h = tid & 63, g = tid >> 6;
        #pragma unroll
        for (int kk = 0; kk < 32; kk++) {
            const int kp = g * 32 + kk;
            const float v0 = gv[(2 * kp) * Hh + h];
            const float v1 = gv[(2 * kp + 1) * Hh + h];
            uint32_t hi, lo;
            split_pair(v0, v1, hi, lo);
            svh[h * 132 + kp] = hi;
            svl[h * 132 + kp] = lo;
        }
    }
    __syncthreads();

    const int w = tid >> 5, lane = tid & 31;
    const int gr = lane >> 2, ct = lane & 3;
    const float scale = rsqrtf((float)Cc);

    const uint32_t* gqh = g_qph + (size_t)b * 8192;
    const uint32_t* gql = g_qpl + (size_t)b * 8192;

    for (int t = 0; t < 2; t++) {
        const int qr0 = w + 8 * gr + 128 * t;    // rows for c0,c1 (a0,a2)
        const int qr1 = qr0 + 64;                // rows for c2,c3 (a1,a3)

        // Q fragments from gmem (hi & lo), 4 ksteps.
        uint32_t qfh[16], qfl[16];
        #pragma unroll
        for (int ks = 0; ks < 4; ks++) {
            const int b0 = qr0 * 32 + 8 * ks + ct;
            const int b1 = qr1 * 32 + 8 * ks + ct;
            qfh[ks*4+0] = gqh[b0];     qfh[ks*4+1] = gqh[b1];
            qfh[ks*4+2] = gqh[b0 + 4]; qfh[ks*4+3] = gqh[b1 + 4];
            qfl[ks*4+0] = gql[b0];     qfl[ks*4+1] = gql[b1];
            qfl[ks*4+2] = gql[b0 + 4]; qfl[ks*4+3] = gql[b1 + 4];
        }

        float m0 = -1e30f, m1 = -1e30f, l0 = 0.f, l1 = 0.f;
        float o[8][4];
        #pragma unroll
        for (int n = 0; n < 8; n++)
            #pragma unroll
            for (int r = 0; r < 4; r++) o[n][r] = 0.f;

        const int nblk = (t == 0) ? 2 : 4;
        for (int jb = 0; jb < nblk; jb++) {
            const int j0 = jb * 64;

            // ---- S = Q K^T (3-pass) ----
            float s[8][4];
            #pragma unroll
            for (int n = 0; n < 8; n++)
                #pragma unroll
                for (int r = 0; r < 4; r++) s[n][r] = 0.f;

            #pragma unroll
            for (int ks = 0; ks < 4; ks++) {
                const int hp = 8 * ks + ct;
                #pragma unroll
                for (int n = 0; n < 8; n++) {
                    const int key = j0 + 8 * n + gr;
                    const uint2 bh = make_uint2(skh[key * 36 + hp], skh[key * 36 + hp + 4]);
                    const uint2 bl = make_uint2(skl[key * 36 + hp], skl[key * 36 + hp + 4]);
                    mma_bf16(s[n], &qfh[ks*4], bh);
                    mma_bf16(s[n], &qfh[ks*4], bl);
                    mma_bf16(s[n], &qfl[ks*4], bh);
                }
            }

            // ---- scale + causal mask + row max ----
            float rm0 = -1e30f, rm1 = -1e30f;
            #pragma unroll
            for (int n = 0; n < 8; n++) {
                const int key0 = j0 + 8 * n + 2 * ct;
                s[n][0] = (key0     <= qr0) ? s[n][0] * scale : -1e30f;
                s[n][1] = (key0 + 1 <= qr0) ? s[n][1] * scale : -1e30f;
                s[n][2] = (key0     <= qr1) ? s[n][2] * scale : -1e30f;
                s[n][3] = (key0 + 1 <= qr1) ? s[n][3] * scale : -1e30f;
                rm0 = fmaxf(rm0, fmaxf(s[n][0], s[n][1]));
                rm1 = fmaxf(rm1, fmaxf(s[n][2], s[n][3]));
            }
            rm0 = fmaxf(rm0, __shfl_xor_sync(0xffffffffu, rm0, 1));
            rm0 = fmaxf(rm0, __shfl_xor_sync(0xffffffffu, rm0, 2));
            rm1 = fmaxf(rm1, __shfl_xor_sync(0xffffffffu, rm1, 1));
            rm1 = fmaxf(rm1, __shfl_xor_sync(0xffffffffu, rm1, 2));

            const float mn0 = fmaxf(m0, rm0), mn1 = fmaxf(m1, rm1);
            const float f0 = __expf(m0 - mn0), f1 = __expf(m1 - mn1);
            m0 = mn0; m1 = mn1;
            l0 *= f0; l1 *= f1;
            #pragma unroll
            for (int n = 0; n < 8; n++) {
                o[n][0] *= f0; o[n][1] *= f0;
                o[n][2] *= f1; o[n][3] *= f1;
            }

            // ---- p = exp(s - m), partial l ----
            #pragma unroll
            for (int n = 0; n < 8; n++) {
                s[n][0] = __expf(s[n][0] - m0);
                s[n][1] = __expf(s[n][1] - m0);
                s[n][2] = __expf(s[n][2] - m1);
                s[n][3] = __expf(s[n][3] - m1);
                l0 += s[n][0] + s[n][1];
                l1 += s[n][2] + s[n][3];
            }

            // ---- O += P V (3-pass) ----
            #pragma unroll
            for (int ks = 0; ks < 4; ks++) {
                uint32_t ph[4], pl[4];
                split_pair(s[2*ks][0],   s[2*ks][1],   ph[0], pl[0]);
                split_pair(s[2*ks][2],   s[2*ks][3],   ph[1], pl[1]);
                split_pair(s[2*ks+1][0], s[2*ks+1][1], ph[2], pl[2]);
                split_pair(s[2*ks+1][2], s[2*ks+1][3], ph[3], pl[3]);
                const int kpb = (j0 >> 1) + 8 * ks + ct;
                #pragma unroll
                for (int hn = 0; hn < 8; hn++) {
                    const int h = hn * 8 + gr;
                    const uint2 vbh = make_uint2(svh[h * 132 + kpb], svh[h * 132 + kpb + 4]);
                    const uint2 vbl = make_uint2(svl[h * 132 + kpb], svl[h * 132 + kpb + 4]);
                    mma_bf16(o[hn], ph, vbh);
                    mma_bf16(o[hn], ph, vbl);
                    mma_bf16(o[hn], pl, vbh);
                }
            }
        }

        // ---- finalize: quad-reduce l, normalize, store ----
        l0 += __shfl_xor_sync(0xffffffffu, l0, 1);
        l0 += __shfl_xor_sync(0xffffffffu, l0, 2);
        l1 += __shfl_xor_sync(0xffffffffu, l1, 1);
        l1 += __shfl_xor_sync(0xffffffffu, l1, 2);
        const float inv0 = 1.0f / l0, inv1 = 1.0f / l1;

        #pragma unroll
        for (int hn = 0; hn < 8; hn++) {
            const int hc = hn * 8 + 2 * ct;
            *(float2*)(out + ((size_t)(b * 256 + qr0)) * Hh + hc) =
                make_float2(o[hn][0] * inv0, o[hn][1] * inv0);
            *(float2*)(out + ((size_t)(b * 256 + qr1)) * Hh + hc) =
                make_float2(o[hn][2] * inv1, o[hn][3] * inv1);
        }
    }
}

// ---------------------------------------------------------------------------
// Launch
// ---------------------------------------------------------------------------
extern "C" void kernel_launch(void* const* d_in, const int* in_sizes, int n_in,
                              void* d_out, int out_size)
{
    const float* x  = (const float*)d_in[0];
    const float* Wq = (const float*)d_in[1];
    const float* Wk = (const float*)d_in[2];
    const float* Wv = (const float*)d_in[3];
    float* out = (float*)d_out;

    (void)in_sizes; (void)n_in; (void)out_size;

    const int proj_smem = PSM_U32 * 4;      // 80 KB
    const int attn_smem = ASM_U32 * 4;      // ~138 KB
    cudaFuncSetAttribute(proj_kernel,
                         cudaFuncAttributeMaxDynamicSharedMemorySize, proj_smem);
    cudaFuncSetAttribute(attn_kernel,
                         cudaFuncAttributeMaxDynamicSharedMemorySize, attn_smem);

    wprep_kernel<<<(NCHUNK * BCHUNK_U32 + 255) / 256, 256>>>(Wq, Wk, Wv);
    proj_kernel<<<BT / 128, 256, proj_smem>>>(x);
    attn_kernel<<<Bb, 256, attn_smem>>>(out);
}

// round 8
// speedup vs baseline: 4.5813x; 1.4348x over previous
#include <cuda_runtime.h>
#include <cuda_fp16.h>
#include <cstdint>

#define Bb 256
#define Tt 256
#define Cc 384
#define Hh 64
#define BT (Bb*Tt)
#define Ncat 192
#define KCH 32
#define NCHUNK (Cc/KCH)        // 12
#define BCHUNK_U32 6144

// Scratch
__device__ float    g_v[BT*Hh];          // V fp32 [row][h]
__device__ uint32_t g_qp[BT*32];         // Q fp16 hi, pairs along h
__device__ uint32_t g_kph[BT*32];        // K fp16 hi
__device__ uint32_t g_kpl[BT*32];        // K fp16 lo
__device__ uint32_t g_Bp[NCHUNK * BCHUNK_U32];

// pack two floats as fp16x2: low half = a, high half = b
__device__ __forceinline__ uint32_t pack_f16(float a, float b) {
    uint32_t r;
    asm("cvt.rn.f16x2.f32 %0, %1, %2;" : "=r"(r) : "f"(b), "f"(a));
    return r;
}

__device__ __forceinline__ void split_pair(float xx, float yy, uint32_t& hi, uint32_t& lo) {
    const float hx = __half2float(__float2half(xx));
    const float hy = __half2float(__float2half(yy));
    hi = pack_f16(xx, yy);
    lo = pack_f16(xx - hx, yy - hy);
}

__device__ __forceinline__ void mma_f16(float* c, const uint32_t* a, uint2 b) {
    asm volatile("mma.sync.aligned.m16n8k16.row.col.f32.f16.f16.f32 "
        "{%0,%1,%2,%3}, {%4,%5,%6,%7}, {%8,%9}, {%0,%1,%2,%3};"
        : "+f"(c[0]), "+f"(c[1]), "+f"(c[2]), "+f"(c[3])
        : "r"(a[0]), "r"(a[1]), "r"(a[2]), "r"(a[3]), "r"(b.x), "r"(b.y));
}

// ---------------------------------------------------------------------------
// Kernel 0: pack W into per-chunk fragment layout, fp16 hi/lo.
// ---------------------------------------------------------------------------
__global__ void wprep_kernel(const float* __restrict__ Wq,
                             const float* __restrict__ Wk,
                             const float* __restrict__ Wv)
{
    const int gid = blockIdx.x * blockDim.x + threadIdx.x;
    if (gid >= NCHUNK * BCHUNK_U32) return;
    const int chunk = gid / BCHUNK_U32;
    const int t  = gid % BCHUNK_U32;
    const int j  = t >> 8;
    const int s  = (t >> 7) & 1;
    const int h  = (t >> 6) & 1;
    const int l  = (t >> 1) & 31;
    const int rr = t & 1;
    const int gr = l >> 2, ct = l & 3;
    const int n  = j * 8 + gr;
    const int k  = chunk * 32 + s * 16 + 2 * ct + rr * 8;
    const float* W = (n < 64) ? Wq : (n < 128) ? Wk : Wv;
    const int hc = n & 63;
    const float w0 = W[k * Hh + hc];
    const float w1 = W[(k + 1) * Hh + hc];
    uint32_t outv;
    if (h == 0) {
        outv = pack_f16(w0, w1);
    } else {
        const float h0 = __half2float(__float2half(w0));
        const float h1 = __half2float(__float2half(w1));
        outv = pack_f16(w0 - h0, w1 - h1);
    }
    g_Bp[gid] = outv;
}

// ---------------------------------------------------------------------------
// Kernel 1: projection via mma.sync fp16 2-pass (A-hi x B-hi + A-hi x B-lo).
// CTA: 128 rows x 192 cols, 8 warps 4(M)x2(N). K in 12 chunks, double-buffered.
// smem (u32): A buf b at b*2048 (hi only); B buf b at 4096 + b*6144.
// ---------------------------------------------------------------------------
#define PSM_U32 (2*2048 + 2*BCHUNK_U32)   // 16384 u32 = 64 KB

extern __shared__ char dynsm[];

__device__ __forceinline__ void ldgA(const float* __restrict__ x, long rowbase,
                                     int c, int tid, float4 av[4]) {
    #pragma unroll
    for (int i = 0; i < 4; i++) {
        const int idx = tid + i * 256;
        const int row = idx >> 3, c4 = idx & 7;
        av[i] = *(const float4*)(x + (rowbase + row) * Cc + c * KCH + c4 * 4);
    }
}

__device__ __forceinline__ void stsA(uint32_t* abuf, int tid, const float4 av[4]) {
    #pragma unroll
    for (int i = 0; i < 4; i++) {
        const int idx = tid + i * 256;
        const int row = idx >> 3, c4 = idx & 7;
        const int k2 = c4 * 2;
        const int base_i = ((row >> 4) * 2 + (k2 >> 3)) * 128;
        const int r = ((row >> 3) & 1) + (((k2 >> 2) & 1) << 1);
        const int lane4 = ((row & 7) << 2) | (k2 & 3);
        const int off = base_i + lane4 * 4 + r;
        abuf[off]     = pack_f16(av[i].x, av[i].y);
        abuf[off + 4] = pack_f16(av[i].z, av[i].w);
    }
}

__device__ __forceinline__ void ldgB(int c, int tid, float4 bv[6]) {
    const float4* src = (const float4*)(g_Bp + c * BCHUNK_U32);
    #pragma unroll
    for (int i = 0; i < 6; i++) bv[i] = src[tid + i * 256];
}

__device__ __forceinline__ void stsB(uint32_t* bbuf, int tid, const float4 bv[6]) {
    float4* dst = (float4*)bbuf;
    #pragma unroll
    for (int i = 0; i < 6; i++) dst[tid + i * 256] = bv[i];
}

__global__ __launch_bounds__(256) void proj_kernel(const float* __restrict__ x)
{
    uint32_t* psm = (uint32_t*)dynsm;
    const int tid  = threadIdx.x;
    const long rowbase = (long)blockIdx.x * 128;
    const int warp = tid >> 5, lane = tid & 31;
    const int mw = warp & 3, nw = warp >> 2;
    const int gr = lane >> 2, ct = lane & 3;

    float acc[2][12][4];
    #pragma unroll
    for (int im = 0; im < 2; im++)
        #pragma unroll
        for (int j = 0; j < 12; j++)
            #pragma unroll
            for (int r = 0; r < 4; r++) acc[im][j][r] = 0.f;

    {
        float4 av[4], bv[6];
        ldgA(x, rowbase, 0, tid, av);
        ldgB(0, tid, bv);
        stsA(psm, tid, av);
        stsB(psm + 4096, tid, bv);
    }
    __syncthreads();

    for (int c = 0; c < NCHUNK; c++) {
        float4 av[4], bv[6];
        const bool more = (c + 1 < NCHUNK);
        if (more) {
            ldgA(x, rowbase, c + 1, tid, av);
            ldgB(c + 1, tid, bv);
        }

        const uint32_t* abuf = psm + (c & 1) * 2048;
        const uint32_t* bbuf = psm + 4096 + (c & 1) * BCHUNK_U32;

        #pragma unroll
        for (int s = 0; s < 2; s++) {
            uint32_t ah[2][4];
            #pragma unroll
            for (int im = 0; im < 2; im++) {
                const int base = ((mw * 2 + im) * 2 + s) * 128 + lane * 4;
                const uint4 vh = *(const uint4*)(abuf + base);
                ah[im][0] = vh.x; ah[im][1] = vh.y; ah[im][2] = vh.z; ah[im][3] = vh.w;
            }
            #pragma unroll
            for (int j = 0; j < 12; j++) {
                const int jj = nw * 12 + j;
                const uint32_t* bp = bbuf + ((jj * 2 + s) * 2) * 64 + lane * 2;
                const uint2 bh = *(const uint2*)(bp);
                const uint2 bl = *(const uint2*)(bp + 64);
                #pragma unroll
                for (int im = 0; im < 2; im++) {
                    mma_f16(acc[im][j], ah[im], bh);   // hi*hi
                    mma_f16(acc[im][j], ah[im], bl);   // hi*lo
                }
            }
        }

        if (more) {
            uint32_t* abn = psm + ((c + 1) & 1) * 2048;
            uint32_t* bbn = psm + 4096 + ((c + 1) & 1) * BCHUNK_U32;
            stsA(abn, tid, av);
            stsB(bbn, tid, bv);
        }
        __syncthreads();
    }

    // Epilogue: q -> fp16 hi pairs; k -> fp16 hi/lo pairs; v -> fp32.
    #pragma unroll
    for (int im = 0; im < 2; im++) {
        #pragma unroll
        for (int j = 0; j < 12; j++) {
            const int jj = nw * 12 + j;
            const int n0 = jj * 8 + 2 * ct;
            const long row0 = rowbase + mw * 32 + im * 16 + gr;
            if (n0 < 64) {
                const int hp = jj * 4 + ct;
                g_qp[row0 * 32 + hp]       = pack_f16(acc[im][j][0], acc[im][j][1]);
                g_qp[(row0 + 8) * 32 + hp] = pack_f16(acc[im][j][2], acc[im][j][3]);
            } else if (n0 < 128) {
                const int hp = (jj & 7) * 4 + ct;
                uint32_t hi0, lo0, hi1, lo1;
                split_pair(acc[im][j][0], acc[im][j][1], hi0, lo0);
                split_pair(acc[im][j][2], acc[im][j][3], hi1, lo1);
                g_kph[row0 * 32 + hp]       = hi0;
                g_kpl[row0 * 32 + hp]       = lo0;
                g_kph[(row0 + 8) * 32 + hp] = hi1;
                g_kpl[(row0 + 8) * 32 + hp] = lo1;
            } else {
                const int hc = n0 & 63;
                *(float2*)(g_v + row0 * Hh + hc)       = make_float2(acc[im][j][0], acc[im][j][1]);
                *(float2*)(g_v + (row0 + 8) * Hh + hc) = make_float2(acc[im][j][2], acc[im][j][3]);
            }
        }
    }
}

// ---------------------------------------------------------------------------
// Kernel 2: flash attention via mma.sync fp16 2-pass.
// 1 CTA per batch, 8 warps; warp w owns rows w + 8i (balanced causal).
// S = qh*(kh+kl); O += ph*(vh+vl).
// ---------------------------------------------------------------------------
#define SKH 0
#define SKL 9216
#define SVH 18432
#define SVL (18432 + 8448)
#define ASM_U32 (18432 + 2*8448)   // 35328 u32 = 141312 B

__global__ __launch_bounds__(256) void attn_kernel(float* __restrict__ out)
{
    uint32_t* sm = (uint32_t*)dynsm;
    uint32_t* skh = sm + SKH;
    uint32_t* skl = sm + SKL;
    uint32_t* svh = sm + SVH;
    uint32_t* svl = sm + SVL;

    const int b   = blockIdx.x;
    const int tid = threadIdx.x;

    // Stage K hi/lo: [256][32] u32 -> [256][36] padded.
    {
        const uint4* gh = (const uint4*)(g_kph + (size_t)b * 8192);
        const uint4* gl = (const uint4*)(g_kpl + (size_t)b * 8192);
        #pragma unroll
        for (int i = 0; i < 8; i++) {
            const int idx = tid + i * 256;
            const int row = idx >> 3, c4 = (idx & 7) * 4;
            *(uint4*)(skh + row * 36 + c4) = gh[idx];
            *(uint4*)(skl + row * 36 + c4) = gl[idx];
        }
    }
    // Stage V: transpose+split fp32 [key][h] -> fp16 pairs [h][keypair].
    {
        const float* gv = g_v + (size_t)b * Tt * Hh;
        const int h = tid & 63, g = tid >> 6;
        #pragma unroll
        for (int kk = 0; kk < 32; kk++) {
            const int kp = g * 32 + kk;
            const float v0 = gv[(2 * kp) * Hh + h];
            const float v1 = gv[(2 * kp + 1) * Hh + h];
            uint32_t hi, lo;
            split_pair(v0, v1, hi, lo);
            svh[h * 132 + kp] = hi;
            svl[h * 132 + kp] = lo;
        }
    }
    __syncthreads();

    const int w = tid >> 5, lane = tid & 31;
    const int gr = lane >> 2, ct = lane & 3;
    const float scale = rsqrtf((float)Cc);

    const uint32_t* gq = g_qp + (size_t)b * 8192;

    for (int t = 0; t < 2; t++) {
        const int qr0 = w + 8 * gr + 128 * t;
        const int qr1 = qr0 + 64;

        uint32_t qf[16];
        #pragma unroll
        for (int ks = 0; ks < 4; ks++) {
            const int b0 = qr0 * 32 + 8 * ks + ct;
            const int b1 = qr1 * 32 + 8 * ks + ct;
            qf[ks*4+0] = gq[b0];     qf[ks*4+1] = gq[b1];
            qf[ks*4+2] = gq[b0 + 4]; qf[ks*4+3] = gq[b1 + 4];
        }

        float m0 = -1e30f, m1 = -1e30f, l0 = 0.f, l1 = 0.f;
        float o[8][4];
        #pragma unroll
        for (int n = 0; n < 8; n++)
            #pragma unroll
            for (int r = 0; r < 4; r++) o[n][r] = 0.f;

        const int nblk = (t == 0) ? 2 : 4;
        for (int jb = 0; jb < nblk; jb++) {
            const int j0 = jb * 64;

            // ---- S = Q K^T (2-pass) ----
            float s[8][4];
            #pragma unroll
            for (int n = 0; n < 8; n++)
                #pragma unroll
                for (int r = 0; r < 4; r++) s[n][r] = 0.f;

            #pragma unroll
            for (int ks = 0; ks < 4; ks++) {
                const int hp = 8 * ks + ct;
                #pragma unroll
                for (int n = 0; n < 8; n++) {
                    const int key = j0 + 8 * n + gr;
                    const uint2 bh = make_uint2(skh[key * 36 + hp], skh[key * 36 + hp + 4]);
                    const uint2 bl = make_uint2(skl[key * 36 + hp], skl[key * 36 + hp + 4]);
                    mma_f16(s[n], &qf[ks*4], bh);
                    mma_f16(s[n], &qf[ks*4], bl);
                }
            }

            // ---- scale + causal mask + row max ----
            float rm0 = -1e30f, rm1 = -1e30f;
            #pragma unroll
            for (int n = 0; n < 8; n++) {
                const int key0 = j0 + 8 * n + 2 * ct;
                s[n][0] = (key0     <= qr0) ? s[n][0] * scale : -1e30f;
                s[n][1] = (key0 + 1 <= qr0) ? s[n][1] * scale : -1e30f;
                s[n][2] = (key0     <= qr1) ? s[n][2] * scale : -1e30f;
                s[n][3] = (key0 + 1 <= qr1) ? s[n][3] * scale : -1e30f;
                rm0 = fmaxf(rm0, fmaxf(s[n][0], s[n][1]));
                rm1 = fmaxf(rm1, fmaxf(s[n][2], s[n][3]));
            }
            rm0 = fmaxf(rm0, __shfl_xor_sync(0xffffffffu, rm0, 1));
            rm0 = fmaxf(rm0, __shfl_xor_sync(0xffffffffu, rm0, 2));
            rm1 = fmaxf(rm1, __shfl_xor_sync(0xffffffffu, rm1, 1));
            rm1 = fmaxf(rm1, __shfl_xor_sync(0xffffffffu, rm1, 2));

            const float mn0 = fmaxf(m0, rm0), mn1 = fmaxf(m1, rm1);
            const float f0 = __expf(m0 - mn0), f1 = __expf(m1 - mn1);
            m0 = mn0; m1 = mn1;
            l0 *= f0; l1 *= f1;
            #pragma unroll
            for (int n = 0; n < 8; n++) {
                o[n][0] *= f0; o[n][1] *= f0;
                o[n][2] *= f1; o[n][3] *= f1;
            }

            // ---- p = exp(s - m), partial l ----
            #pragma unroll
            for (int n = 0; n < 8; n++) {
                s[n][0] = __expf(s[n][0] - m0);
                s[n][1] = __expf(s[n][1] - m0);
                s[n][2] = __expf(s[n][2] - m1);
                s[n][3] = __expf(s[n][3] - m1);
                l0 += s[n][0] + s[n][1];
                l1 += s[n][2] + s[n][3];
            }

            // ---- O += P V (2-pass; P fp16 single precision) ----
            #pragma unroll
            for (int ks = 0; ks < 4; ks++) {
                uint32_t ph[4];
                ph[0] = pack_f16(s[2*ks][0],   s[2*ks][1]);
                ph[1] = pack_f16(s[2*ks][2],   s[2*ks][3]);
                ph[2] = pack_f16(s[2*ks+1][0], s[2*ks+1][1]);
                ph[3] = pack_f16(s[2*ks+1][2], s[2*ks+1][3]);
                const int kpb = (j0 >> 1) + 8 * ks + ct;
                #pragma unroll
                for (int hn = 0; hn < 8; hn++) {
                    const int h = hn * 8 + gr;
                    const uint2 vbh = make_uint2(svh[h * 132 + kpb], svh[h * 132 + kpb + 4]);
                    const uint2 vbl = make_uint2(svl[h * 132 + kpb], svl[h * 132 + kpb + 4]);
                    mma_f16(o[hn], ph, vbh);
                    mma_f16(o[hn], ph, vbl);
                }
            }
        }

        l0 += __shfl_xor_sync(0xffffffffu, l0, 1);
        l0 += __shfl_xor_sync(0xffffffffu, l0, 2);
        l1 += __shfl_xor_sync(0xffffffffu, l1, 1);
        l1 += __shfl_xor_sync(0xffffffffu, l1, 2);
        const float inv0 = 1.0f / l0, inv1 = 1.0f / l1;

        #pragma unroll
        for (int hn = 0; hn < 8; hn++) {
            const int hc = hn * 8 + 2 * ct;
            *(float2*)(out + ((size_t)(b * 256 + qr0)) * Hh + hc) =
                make_float2(o[hn][0] * inv0, o[hn][1] * inv0);
            *(float2*)(out + ((size_t)(b * 256 + qr1)) * Hh + hc) =
                make_float2(o[hn][2] * inv1, o[hn][3] * inv1);
        }
    }
}

// ---------------------------------------------------------------------------
// Launch
// ---------------------------------------------------------------------------
extern "C" void kernel_launch(void* const* d_in, const int* in_sizes, int n_in,
                              void* d_out, int out_size)
{
    const float* x  = (const float*)d_in[0];
    const float* Wq = (const float*)d_in[1];
    const float* Wk = (const float*)d_in[2];
    const float* Wv = (const float*)d_in[3];
    float* out = (float*)d_out;

    (void)in_sizes; (void)n_in; (void)out_size;

    const int proj_smem = PSM_U32 * 4;      // 64 KB
    const int attn_smem = ASM_U32 * 4;      // ~138 KB
    cudaFuncSetAttribute(proj_kernel,
                         cudaFuncAttributeMaxDynamicSharedMemorySize, proj_smem);
    cudaFuncSetAttribute(attn_kernel,
                         cudaFuncAttributeMaxDynamicSharedMemorySize, attn_smem);

    wprep_kernel<<<(NCHUNK * BCHUNK_U32 + 255) / 256, 256>>>(Wq, Wk, Wv);
    proj_kernel<<<BT / 128, 256, proj_smem>>>(x);
    attn_kernel<<<Bb, 256, attn_smem>>>(out);
}